// round 14
// baseline (speedup 1.0000x reference)
#include <cuda_runtime.h>
#include <cuda_bf16.h>
#include <math.h>
#include <stdint.h>

#define B_  64
#define N_  900   // queries
#define C_  91    // classes
#define M_  128   // targets

#define INF_D 1e18
#define FULLM 0xFFFFFFFFu
#define TLSA 256
#define MT   8     // targets per cost-block

// Scratch (allocation-free rule: __device__ globals)
__device__ float g_costT[(size_t)B_ * M_ * N_];   // [b][m][n]
__device__ float g_probT[(size_t)B_ * C_ * N_];   // [b][c][n]  transposed probs

// Monotonic double->uint64 map: preserves < order for all non-NaN doubles.
__device__ __forceinline__ unsigned long long dmap(double d) {
    unsigned long long x = __double_as_longlong(d);
    return (x & 0x8000000000000000ull) ? ~x : (x | 0x8000000000000000ull);
}
__device__ __forceinline__ double dunmap(unsigned long long k) {
    return (k & 0x8000000000000000ull)
        ? __longlong_as_double(k & 0x7FFFFFFFFFFFFFFFull)
        : __longlong_as_double(~k);
}

// ---------------------------------------------------------------------------
// Kernel 1: full softmax probabilities, written TRANSPOSED: probT[b][c][n].
// Block = 256 threads handles 32 query rows of one batch; smem transpose
// makes both the logits reads and probT writes coalesced.
// ---------------------------------------------------------------------------
__global__ void prob_kernel(const float* __restrict__ logits) {
    int b = blockIdx.y;
    int n0 = blockIdx.x * 32;
    int rows = min(32, N_ - n0);
    int tid = threadIdx.x;
    int w = tid >> 5, lane = tid & 31;

    __shared__ float tile[32][C_];   // exp(l - mx) per (row, class)
    __shared__ float inv[32];

    // warp per row: max, then exp + sum (exps kept in tile)
    for (int r = w; r < rows; r += 8) {
        const float* row = logits + ((size_t)b * N_ + n0 + r) * C_;
        float mx = -INFINITY;
        for (int c = lane; c < C_; c += 32) mx = fmaxf(mx, row[c]);
        #pragma unroll
        for (int o = 16; o; o >>= 1) mx = fmaxf(mx, __shfl_xor_sync(FULLM, mx, o));

        float s = 0.f;
        for (int c = lane; c < C_; c += 32) {
            float e = expf(row[c] - mx);
            tile[r][c] = e;
            s += e;
        }
        #pragma unroll
        for (int o = 16; o; o >>= 1) s += __shfl_xor_sync(FULLM, s, o);
        if (lane == 0) inv[r] = 1.0f / s;
    }
    __syncthreads();

    // transposed write: probT[b][c][n0+r], r fastest -> coalesced
    for (int idx = tid; idx < C_ * 32; idx += 256) {
        int c = idx >> 5, r = idx & 31;
        if (r < rows)
            g_probT[((size_t)b * C_ + c) * N_ + n0 + r] = tile[r][c] * inv[r];
    }
}

// ---------------------------------------------------------------------------
// Kernel 2: cost matrix, transposed layout costT[b][m][n].
// Block handles MT=8 targets; prob reads coalesced from probT; pboxes via
// float4, amortized across the 8 targets.
// ---------------------------------------------------------------------------
__global__ void cost_kernel(const float* __restrict__ pboxes,
                            const int* __restrict__ tlabels,
                            const float* __restrict__ tboxes) {
    int m0 = blockIdx.x * MT;
    int b = blockIdx.y;
    int tid = threadIdx.x;

    __shared__ int   scls[MT];
    __shared__ float stb[MT][4];     // tcx, tcy, tw, th
    __shared__ float sta[MT];        // tarea

    if (tid < MT) {
        int idx = b * M_ + m0 + tid;
        scls[tid] = tlabels[idx];
        const float* tbp = tboxes + (size_t)idx * 4;
        float tcx = tbp[0], tcy = tbp[1], tw = tbp[2], th = tbp[3];
        stb[tid][0] = tcx; stb[tid][1] = tcy; stb[tid][2] = tw; stb[tid][3] = th;
        sta[tid] = tw * th;          // (tx1-tx0)*(ty1-ty0) == tw*th
    }
    __syncthreads();

    const float4* pb4 = (const float4*)(pboxes + (size_t)b * N_ * 4);

    for (int n = tid; n < N_; n += 256) {
        float4 p = pb4[n];
        float pcx = p.x, pcy = p.y, pw = p.z, ph = p.w;
        float px0 = pcx - 0.5f * pw, py0 = pcy - 0.5f * ph;
        float px1 = pcx + 0.5f * pw, py1 = pcy + 0.5f * ph;
        float area1 = pw * ph;

        #pragma unroll
        for (int mi = 0; mi < MT; ++mi) {
            float tcx = stb[mi][0], tcy = stb[mi][1];
            float tw = stb[mi][2], th = stb[mi][3];
            float tx0 = tcx - 0.5f * tw, ty0 = tcy - 0.5f * th;
            float tx1 = tcx + 0.5f * tw, ty1 = tcy + 0.5f * th;

            float prob = g_probT[((size_t)b * C_ + scls[mi]) * N_ + n];

            float l1 = fabsf(pcx - tcx) + fabsf(pcy - tcy)
                     + fabsf(pw - tw) + fabsf(ph - th);

            float iw = fmaxf(fminf(px1, tx1) - fmaxf(px0, tx0), 0.f);
            float ih = fmaxf(fminf(py1, ty1) - fmaxf(py0, ty0), 0.f);
            float inter = iw * ih;
            float uni = area1 + sta[mi] - inter;
            float iou = inter / (uni + 1e-6f);
            float enc = (fmaxf(px1, tx1) - fminf(px0, tx0)) *
                        (fmaxf(py1, ty1) - fminf(py0, ty0)) + 1e-6f;
            float giou = iou - (enc - uni) / enc;

            g_costT[((size_t)(b * M_ + m0 + mi)) * N_ + n] =
                -prob + 5.f * l1 - 2.f * giou;
        }
    }
}

// ---------------------------------------------------------------------------
// Kernel 3: Hungarian (greedy init + successive shortest paths), block per
// batch. Emits float32 rows/cols directly (harness compares float32).
// ---------------------------------------------------------------------------
__global__ void __launch_bounds__(TLSA, 1)
lsa_block_kernel(float* __restrict__ rows_out, float* __restrict__ cols_out) {
    int b = blockIdx.x;
    int tid = threadIdx.x;
    const float* cost = g_costT + (size_t)b * M_ * N_;

    __shared__ double u[M_ + 1];
    __shared__ int    p[N_ + 1];
    __shared__ int    way[N_ + 1];
    __shared__ float  rmin[M_];
    __shared__ int    rarg[M_];
    __shared__ int    owner[N_];
    __shared__ int    freelist[M_];
    __shared__ int    nfree_sh;
    __shared__ unsigned long long red_k[TLSA / 32];
    __shared__ int    red_j[TLSA / 32];
    __shared__ int    j0_sh, done_sh;
    __shared__ double delta_sh;
    __shared__ int    col4row[M_];

    const int cA = tid, cB = tid + 256, cC = tid + 512, cD = tid + 768;
    const bool ownD = (cD < N_);

    for (int j = tid; j <= N_; j += TLSA) p[j] = 0;
    for (int j = tid; j < N_; j += TLSA) owner[j] = 0x7FFFFFFF;
    __syncthreads();

    // ---- Phase 1: row minima (8 warps x 16 rows) ----
    {
        int w = tid >> 5, lane = tid & 31;
        for (int i = w; i < M_; i += TLSA / 32) {
            const float* crow = cost + (size_t)i * N_;
            float best = 1e30f; int bj = N_;
            for (int j = lane; j < N_; j += 32) {
                float c = crow[j];
                if (c < best || (c == best && j < bj)) { best = c; bj = j; }
            }
            #pragma unroll
            for (int o = 16; o; o >>= 1) {
                float ov = __shfl_down_sync(FULLM, best, o);
                int oj = __shfl_down_sync(FULLM, bj, o);
                if (ov < best || (ov == best && oj < bj)) { best = ov; bj = oj; }
            }
            if (lane == 0) { rmin[i] = best; rarg[i] = bj; }
        }
    }
    __syncthreads();

    if (tid < M_) {
        u[tid + 1] = (double)rmin[tid];
        atomicMin(&owner[rarg[tid]], tid);
    }
    if (tid == 0) u[0] = 0.0;
    __syncthreads();

    if (tid == 0) {
        int nf = 0;
        for (int i = 0; i < M_; ++i) {
            int j = rarg[i];
            if (owner[j] == i) p[j + 1] = i + 1;
            else               freelist[nf++] = i + 1;
        }
        nfree_sh = nf;
    }
    __syncthreads();
    int nfree = nfree_sh;

    // ---- Phase 2: augment remaining rows ----
    double vA = 0.0, vB = 0.0, vC = 0.0, vD = 0.0;
    double mA, mB, mC, mD;
    unsigned um;

    for (int k = 0; k < nfree; ++k) {
        int i = freelist[k];
        if (tid == 0) { p[0] = i; j0_sh = 0; done_sh = 0; }
        mA = INF_D; mB = INF_D; mC = INF_D; mD = INF_D;
        um = 0;
        bool first = true;

        while (true) {
            __syncthreads();                 // barrier A
            int j0 = j0_sh;

            if (!first) {
                double delta = delta_sh;
                if (um & 1u) { vA -= delta; u[p[cA + 1]] += delta; } else mA -= delta;
                if (um & 2u) { vB -= delta; u[p[cB + 1]] += delta; } else mB -= delta;
                if (um & 4u) { vC -= delta; u[p[cC + 1]] += delta; } else mC -= delta;
                if (ownD) {
                    if (um & 8u) { vD -= delta; u[p[cD + 1]] += delta; } else mD -= delta;
                }
            }
            if (done_sh) break;
            first = false;

            if (j0 >= 1) {
                int c = j0 - 1;
                if ((c & 255) == tid) um |= 1u << (c >> 8);
            }

            int i0 = p[j0];
            const float* crow = cost + (size_t)(i0 - 1) * N_;
            float fA = crow[cA];
            float fB = crow[cB];
            float fC = crow[cC];
            float fD = ownD ? crow[cD] : 0.f;
            double ui0 = u[i0];

            unsigned long long bk = 0xFFFFFFFFFFFFFFFFull;
            int bj = N_ + 2;
            if (!(um & 1u)) {
                double cur = (double)fA - ui0 - vA;
                if (cur < mA) { mA = cur; way[cA + 1] = j0; }
                unsigned long long kk = dmap(mA);
                if (kk < bk) { bk = kk; bj = cA + 1; }
            }
            if (!(um & 2u)) {
                double cur = (double)fB - ui0 - vB;
                if (cur < mB) { mB = cur; way[cB + 1] = j0; }
                unsigned long long kk = dmap(mB);
                if (kk < bk || (kk == bk && cB + 1 < bj)) { bk = kk; bj = cB + 1; }
            }
            if (!(um & 4u)) {
                double cur = (double)fC - ui0 - vC;
                if (cur < mC) { mC = cur; way[cC + 1] = j0; }
                unsigned long long kk = dmap(mC);
                if (kk < bk || (kk == bk && cC + 1 < bj)) { bk = kk; bj = cC + 1; }
            }
            if (ownD && !(um & 8u)) {
                double cur = (double)fD - ui0 - vD;
                if (cur < mD) { mD = cur; way[cD + 1] = j0; }
                unsigned long long kk = dmap(mD);
                if (kk < bk || (kk == bk && cD + 1 < bj)) { bk = kk; bj = cD + 1; }
            }

            #pragma unroll
            for (int o = 16; o; o >>= 1) {
                unsigned long long ok = __shfl_down_sync(FULLM, bk, o);
                int oj = __shfl_down_sync(FULLM, bj, o);
                if (ok < bk || (ok == bk && oj < bj)) { bk = ok; bj = oj; }
            }
            if ((tid & 31) == 0) { red_k[tid >> 5] = bk; red_j[tid >> 5] = bj; }
            __syncthreads();                 // barrier B

            if (tid < 32) {
                unsigned long long fk = (tid < TLSA / 32) ? red_k[tid]
                                                          : 0xFFFFFFFFFFFFFFFFull;
                int fj = (tid < TLSA / 32) ? red_j[tid] : N_ + 2;
                #pragma unroll
                for (int o = 4; o; o >>= 1) {
                    unsigned long long ok = __shfl_down_sync(FULLM, fk, o);
                    int oj = __shfl_down_sync(FULLM, fj, o);
                    if (ok < fk || (ok == fk && oj < fj)) { fk = ok; fj = oj; }
                }
                if (tid == 0) {
                    double delta = dunmap(fk);
                    delta_sh = delta;
                    u[p[0]] += delta;
                    j0_sh = fj;
                    done_sh = (p[fj] == 0);
                }
            }
        }

        if (tid == 0) {
            int jj = j0_sh;
            while (jj) { int jn = way[jj]; p[jj] = p[jn]; jj = jn; }
        }
    }
    __syncthreads();

    for (int j = 1 + tid; j <= N_; j += TLSA)
        if (p[j] > 0) col4row[p[j] - 1] = j - 1;
    __syncthreads();

    // emit float32 directly: rows = sorted assigned queries, cols = targets
    if (tid < M_) {
        int vme = col4row[tid];
        int r = 0;
        #pragma unroll 8
        for (int k = 0; k < M_; ++k) r += (col4row[k] < vme);
        rows_out[b * M_ + r] = (float)vme;
        cols_out[b * M_ + r] = (float)tid;
    }
}

// ---------------------------------------------------------------------------
extern "C" void kernel_launch(void* const* d_in, const int* in_sizes, int n_in,
                              void* d_out, int out_size) {
    const float* logits  = (const float*)d_in[0];
    const float* pboxes  = (const float*)d_in[1];
    const int*   tlabels = (const int*)d_in[2];
    const float* tboxes  = (const float*)d_in[3];

    float* rows_out = (float*)d_out;
    float* cols_out = (float*)d_out + B_ * M_;

    {
        dim3 grid((N_ + 31) / 32, B_);
        prob_kernel<<<grid, 256>>>(logits);
    }
    {
        dim3 grid(M_ / MT, B_);
        cost_kernel<<<grid, 256>>>(pboxes, tlabels, tboxes);
    }
    lsa_block_kernel<<<B_, TLSA>>>(rows_out, cols_out);
}

// round 15
// speedup vs baseline: 1.1683x; 1.1683x over previous
#include <cuda_runtime.h>
#include <cuda_bf16.h>
#include <math.h>
#include <stdint.h>

#define B_  64
#define N_  900   // queries
#define C_  91    // classes
#define M_  128   // targets

#define INF_D 1e18
#define FULLM 0xFFFFFFFFu
#define MT   8

// Scratch (allocation-free rule: __device__ globals)
__device__ float g_costT[(size_t)B_ * M_ * N_];   // [b][m][n]
__device__ float g_probT[(size_t)B_ * C_ * N_];   // [b][c][n]

// Monotonic double->uint64 map (order-preserving for finite doubles).
__device__ __forceinline__ unsigned long long dmap(double d) {
    long long x = __double_as_longlong(d);
    return (unsigned long long)(x ^ ((x >> 63) | 0x8000000000000000ll));
}
__device__ __forceinline__ double dunmap(unsigned long long k) {
    long long x = (long long)k;
    x ^= ((~x) >> 63) | 0x8000000000000000ll;
    return __longlong_as_double(x);
}

// ---------------------------------------------------------------------------
// Kernel 1: softmax probabilities, transposed probT[b][c][n].
// ---------------------------------------------------------------------------
__global__ void prob_kernel(const float* __restrict__ logits) {
    int b = blockIdx.y;
    int n0 = blockIdx.x * 32;
    int rows = min(32, N_ - n0);
    int tid = threadIdx.x;
    int w = tid >> 5, lane = tid & 31;

    __shared__ float tile[32][C_];
    __shared__ float inv[32];

    for (int r = w; r < rows; r += 8) {
        const float* row = logits + ((size_t)b * N_ + n0 + r) * C_;
        float mx = -INFINITY;
        for (int c = lane; c < C_; c += 32) mx = fmaxf(mx, row[c]);
        #pragma unroll
        for (int o = 16; o; o >>= 1) mx = fmaxf(mx, __shfl_xor_sync(FULLM, mx, o));

        float s = 0.f;
        for (int c = lane; c < C_; c += 32) {
            float e = expf(row[c] - mx);
            tile[r][c] = e;
            s += e;
        }
        #pragma unroll
        for (int o = 16; o; o >>= 1) s += __shfl_xor_sync(FULLM, s, o);
        if (lane == 0) inv[r] = 1.0f / s;
    }
    __syncthreads();

    for (int idx = tid; idx < C_ * 32; idx += 256) {
        int c = idx >> 5, r = idx & 31;
        if (r < rows)
            g_probT[((size_t)b * C_ + c) * N_ + n0 + r] = tile[r][c] * inv[r];
    }
}

// ---------------------------------------------------------------------------
// Kernel 2: cost matrix, transposed layout costT[b][m][n], MT targets/block.
// ---------------------------------------------------------------------------
__global__ void cost_kernel(const float* __restrict__ pboxes,
                            const int* __restrict__ tlabels,
                            const float* __restrict__ tboxes) {
    int m0 = blockIdx.x * MT;
    int b = blockIdx.y;
    int tid = threadIdx.x;

    __shared__ int   scls[MT];
    __shared__ float stb[MT][4];
    __shared__ float sta[MT];

    if (tid < MT) {
        int idx = b * M_ + m0 + tid;
        scls[tid] = tlabels[idx];
        const float* tbp = tboxes + (size_t)idx * 4;
        stb[tid][0] = tbp[0]; stb[tid][1] = tbp[1];
        stb[tid][2] = tbp[2]; stb[tid][3] = tbp[3];
        sta[tid] = tbp[2] * tbp[3];
    }
    __syncthreads();

    const float4* pb4 = (const float4*)(pboxes + (size_t)b * N_ * 4);

    for (int n = tid; n < N_; n += 256) {
        float4 p = pb4[n];
        float pcx = p.x, pcy = p.y, pw = p.z, ph = p.w;
        float px0 = pcx - 0.5f * pw, py0 = pcy - 0.5f * ph;
        float px1 = pcx + 0.5f * pw, py1 = pcy + 0.5f * ph;
        float area1 = pw * ph;

        #pragma unroll
        for (int mi = 0; mi < MT; ++mi) {
            float tcx = stb[mi][0], tcy = stb[mi][1];
            float tw = stb[mi][2], th = stb[mi][3];
            float tx0 = tcx - 0.5f * tw, ty0 = tcy - 0.5f * th;
            float tx1 = tcx + 0.5f * tw, ty1 = tcy + 0.5f * th;

            float prob = g_probT[((size_t)b * C_ + scls[mi]) * N_ + n];

            float l1 = fabsf(pcx - tcx) + fabsf(pcy - tcy)
                     + fabsf(pw - tw) + fabsf(ph - th);

            float iw = fmaxf(fminf(px1, tx1) - fmaxf(px0, tx0), 0.f);
            float ih = fmaxf(fminf(py1, ty1) - fmaxf(py0, ty0), 0.f);
            float inter = iw * ih;
            float uni = area1 + sta[mi] - inter;
            float iou = inter / (uni + 1e-6f);
            float enc = (fmaxf(px1, tx1) - fminf(px0, tx0)) *
                        (fmaxf(py1, ty1) - fminf(py0, ty0)) + 1e-6f;
            float giou = iou - (enc - uni) / enc;

            g_costT[((size_t)(b * M_ + m0 + mi)) * N_ + n] =
                -prob + 5.f * l1 - 2.f * giou;
        }
    }
}

// ---------------------------------------------------------------------------
// Kernel 3: Hungarian, scipy-style shortest-path augmentation.
// Phase 1: row-reduction duals + greedy assignment.
// Phase 2: per free row, Dijkstra with running minVal; duals rewritten once
// per augmentation from the used set. One barrier per inner iteration
// (double-buffered reduction slots; redundant stage-2 in every warp).
// Produces THE optimal assignment (unique optimum => matches reference).
// ---------------------------------------------------------------------------
__global__ void __launch_bounds__(256, 1)
lsa_kernel(float* __restrict__ rows_out, float* __restrict__ cols_out) {
    int b = blockIdx.x;
    int tid = threadIdx.x;
    int w = tid >> 5, lane = tid & 31;
    const float* cost = g_costT + (size_t)b * M_ * N_;

    __shared__ double u[M_];
    __shared__ int    row4col[N_];   // col -> row (-1 free)
    __shared__ int    col4row[M_];   // row -> col (-1 free)
    __shared__ int    pathv[N_];     // col -> predecessor row
    __shared__ float  rmin[M_];
    __shared__ int    rarg[M_];
    __shared__ int    owner[N_];
    __shared__ int    freelist[M_];
    __shared__ int    nfree_sh;
    __shared__ unsigned long long redk[2][8];
    __shared__ int    redj[2][8];

    const int cols0 = tid, cols1 = tid + 256, cols2 = tid + 512, cols3 = tid + 768;
    const bool has3 = (cols3 < N_);
    const unsigned long long KINF = dmap(INF_D);

    for (int j = tid; j < N_; j += 256) { row4col[j] = -1; owner[j] = 0x7FFFFFFF; }
    __syncthreads();

    // ---- Phase 1: row minima ----
    for (int i = w; i < M_; i += 8) {
        const float* crow = cost + (size_t)i * N_;
        float best = 1e30f; int bj = 0;
        for (int j = lane; j < N_; j += 32) {
            float c = crow[j];
            if (c < best || (c == best && j < bj)) { best = c; bj = j; }
        }
        #pragma unroll
        for (int o = 16; o; o >>= 1) {
            float ov = __shfl_down_sync(FULLM, best, o);
            int oj = __shfl_down_sync(FULLM, bj, o);
            if (ov < best || (ov == best && oj < bj)) { best = ov; bj = oj; }
        }
        if (lane == 0) { rmin[i] = best; rarg[i] = bj; }
    }
    __syncthreads();

    if (tid < M_) {
        u[tid] = (double)rmin[tid];
        atomicMin(&owner[rarg[tid]], tid);
    }
    __syncthreads();

    if (tid == 0) {
        int nf = 0;
        for (int i = 0; i < M_; ++i) {
            int j = rarg[i];
            if (owner[j] == i) { row4col[j] = i; col4row[i] = j; }
            else               { col4row[i] = -1; freelist[nf++] = i; }
        }
        nfree_sh = nf;
    }
    __syncthreads();
    int nfree = nfree_sh;

    // ---- Phase 2: shortest-path augmentation per free row ----
    double vv[4] = {0.0, 0.0, 0.0, 0.0};

    for (int f = 0; f < nfree; ++f) {
        int istart = freelist[f];
        unsigned long long ks[4] = {KINF, KINF, KINF, KINF};
        unsigned um = has3 ? 0u : 8u;    // fake-used for invalid slot 3
        double minVal = 0.0;
        int cur_i = istart;
        int sink;
        int par = 0;

        for (;;) {
            double ui = u[cur_i];
            const float* crow = cost + (size_t)cur_i * N_;

            unsigned long long bk = 0xFFFFFFFFFFFFFFFFull;
            int bj = 1 << 30;
            // slot 0
            if (!(um & 1u)) {
                double r = minVal + (double)crow[cols0] - ui - vv[0];
                unsigned long long kr = dmap(r);
                if (kr < ks[0]) { ks[0] = kr; pathv[cols0] = cur_i; }
                if (ks[0] < bk) { bk = ks[0]; bj = cols0; }
            }
            // slot 1
            if (!(um & 2u)) {
                double r = minVal + (double)crow[cols1] - ui - vv[1];
                unsigned long long kr = dmap(r);
                if (kr < ks[1]) { ks[1] = kr; pathv[cols1] = cur_i; }
                if (ks[1] < bk) { bk = ks[1]; bj = cols1; }
            }
            // slot 2
            if (!(um & 4u)) {
                double r = minVal + (double)crow[cols2] - ui - vv[2];
                unsigned long long kr = dmap(r);
                if (kr < ks[2]) { ks[2] = kr; pathv[cols2] = cur_i; }
                if (ks[2] < bk) { bk = ks[2]; bj = cols2; }
            }
            // slot 3
            if (!(um & 8u)) {
                double r = minVal + (double)crow[cols3] - ui - vv[3];
                unsigned long long kr = dmap(r);
                if (kr < ks[3]) { ks[3] = kr; pathv[cols3] = cur_i; }
                if (ks[3] < bk) { bk = ks[3]; bj = cols3; }
            }

            // warp reduce (min key, then min col)
            #pragma unroll
            for (int o = 16; o; o >>= 1) {
                unsigned long long ok = __shfl_down_sync(FULLM, bk, o);
                int oj = __shfl_down_sync(FULLM, bj, o);
                if (ok < bk || (ok == bk && oj < bj)) { bk = ok; bj = oj; }
            }
            if (lane == 0) { redk[par][w] = bk; redj[par][w] = bj; }
            __syncthreads();                 // the ONLY barrier per iteration

            // redundant stage-2: every thread reduces the 8 slots locally
            unsigned long long mk = redk[par][0]; int mj = redj[par][0];
            #pragma unroll
            for (int q = 1; q < 8; ++q) {
                unsigned long long qk = redk[par][q]; int qj = redj[par][q];
                if (qk < mk || (qk == mk && qj < mj)) { mk = qk; mj = qj; }
            }
            par ^= 1;
            minVal = dunmap(mk);
            int jmin = mj;

            // mark used (owner thread)
            if ((jmin & 255) == tid) um |= 1u << (jmin >> 8);

            int r4 = row4col[jmin];          // stable during Dijkstra
            if (r4 < 0) { sink = jmin; break; }
            cur_i = r4;
        }

        // ---- dual update from used set (reads OLD row4col) ----
        #pragma unroll
        for (int k = 0; k < 4; ++k) {
            bool genuine = (um & (1u << k)) && (k < 3 || has3);
            if (genuine) {
                int j = tid + (k << 8);
                double sh = dunmap(ks[k]);
                double dv = minVal - sh;
                vv[k] -= dv;
                u[row4col[j]] += dv;         // distinct rows -> no conflict
            }
        }
        __syncthreads();                     // old row4col fully consumed

        if (tid == 0) {
            u[istart] += minVal;
            int j = sink;
            for (;;) {
                int i2 = pathv[j];
                row4col[j] = i2;
                int jn = col4row[i2];
                col4row[i2] = j;
                if (i2 == istart) break;
                j = jn;
            }
        }
        __syncthreads();
    }

    // ---- output: rows = sorted assigned queries, cols = target order ----
    if (tid < M_) {
        int vme = col4row[tid];
        int r = 0;
        #pragma unroll 8
        for (int k = 0; k < M_; ++k) r += (col4row[k] < vme);
        rows_out[b * M_ + r] = (float)vme;
        cols_out[b * M_ + r] = (float)tid;
    }
}

// ---------------------------------------------------------------------------
extern "C" void kernel_launch(void* const* d_in, const int* in_sizes, int n_in,
                              void* d_out, int out_size) {
    const float* logits  = (const float*)d_in[0];
    const float* pboxes  = (const float*)d_in[1];
    const int*   tlabels = (const int*)d_in[2];
    const float* tboxes  = (const float*)d_in[3];

    float* rows_out = (float*)d_out;
    float* cols_out = (float*)d_out + B_ * M_;

    {
        dim3 grid((N_ + 31) / 32, B_);
        prob_kernel<<<grid, 256>>>(logits);
    }
    {
        dim3 grid(M_ / MT, B_);
        cost_kernel<<<grid, 256>>>(pboxes, tlabels, tboxes);
    }
    lsa_kernel<<<B_, 256>>>(rows_out, cols_out);
}